// round 3
// baseline (speedup 1.0000x reference)
#include <cuda_runtime.h>

#define BB 256
#define SS 1024
#define NT 128
#define NB 2

__device__ float g_logZ[BB];
__device__ float g_score[BB];

static __device__ __forceinline__ unsigned long long pk2(float x, float y) {
    unsigned long long r;
    asm("mov.b64 %0, {%1, %2};" : "=l"(r) : "f"(x), "f"(y));
    return r;
}
static __device__ __forceinline__ void upk2(float& x, float& y, unsigned long long v) {
    asm("mov.b64 {%0, %1}, %2;" : "=f"(x), "=f"(y) : "l"(v));
}
static __device__ __forceinline__ void ffma2(unsigned long long& d, unsigned long long a, unsigned long long b) {
    asm("fma.rn.f32x2 %0, %1, %2, %0;" : "+l"(d) : "l"(a), "l"(b));
}

// Padded alpha index: shifts each 32-float i-group by 4 floats so the four
// ig-groups' LDS.128 accesses hit distinct bank quads (conflict-free).
#define AIDX(i) ((i) + (((i) >> 5) << 2))

// Forward recurrence. Grid: 128 CTAs x 256 threads, NB=2 batches per CTA.
// Thread (ig = tid&3, jg = tid>>2) owns exp(T) tile rows [32*ig, 32*ig+32) x
// cols {2*jg, 2*jg+1} in registers, packed as f32x2 over adjacent i.
__global__ __launch_bounds__(256) void crf_forward(
    const float* __restrict__ em, const float* __restrict__ tr,
    const float* __restrict__ mask)
{
    __shared__ __align__(16) float sA[2][NB][144];
    __shared__ __align__(16) float sW[NB][8];

    const int tid  = threadIdx.x;
    const int ig   = tid & 3;
    const int jg   = tid >> 2;
    const int i0   = ig << 5;
    const int j0   = jg << 1;
    const int lane = tid & 31;
    const int wid  = tid >> 5;
    const int b0   = blockIdx.x * NB;

    // exp(T) tile -> registers (one-time; T is L2-resident across all CTAs)
    unsigned long long Ea[16], Eb[16];
#pragma unroll
    for (int k = 0; k < 16; ++k) {
        float2 r0 = *(const float2*)(tr + (i0 + 2 * k) * NT + j0);
        float2 r1 = *(const float2*)(tr + (i0 + 2 * k + 1) * NT + j0);
        Ea[k] = pk2(__expf(r0.x), __expf(r1.x));
        Eb[k] = pk2(__expf(r0.y), __expf(r1.y));
    }

    float lg[NB];
    // t = 0 init: alpha = exp(emissions[:,0,:])
#pragma unroll
    for (int b = 0; b < NB; ++b) {
        lg[b] = 0.0f;
        float2 e0 = *(const float2*)(em + ((size_t)(b0 + b) * SS) * NT + j0);
        float va = __expf(e0.x), vb = __expf(e0.y);
        if (ig == 0) *(float2*)&sA[0][b][AIDX(j0)] = make_float2(va, vb);
    }
    __syncthreads();

    // 2-deep emission/mask prefetch pipeline (issue-to-use > DRAM latency)
    float2 emP0[NB], emP1[NB];
    float  mkP0[NB], mkP1[NB];
#pragma unroll
    for (int b = 0; b < NB; ++b) {
        const float* eb = em + ((size_t)(b0 + b) * SS) * NT;
        emP0[b] = *(const float2*)(eb + 1 * NT + j0);
        emP1[b] = *(const float2*)(eb + 2 * NT + j0);
        mkP0[b] = mask[(b0 + b) * SS + 1];
        mkP1[b] = mask[(b0 + b) * SS + 2];
    }

    for (int t = 1; t < SS; ++t) {
        const int cur = t & 1, prv = cur ^ 1;

        // prefetch t+2 (clamped tail; redundant loads are harmless)
        float2 emN[NB]; float mkN[NB];
        const int tp = (t + 2 < SS) ? (t + 2) : (SS - 1);
#pragma unroll
        for (int b = 0; b < NB; ++b) {
            emN[b] = *(const float2*)(em + ((size_t)(b0 + b) * SS + tp) * NT + j0);
            mkN[b] = mask[(b0 + b) * SS + tp];
        }

        // renorm divisor from maxima published 1 step ago (every 4th step)
        const bool renorm = ((t & 3) == 0);
        float rinv[NB], Mv[NB];
        if (renorm) {
#pragma unroll
            for (int b = 0; b < NB; ++b) {
                float4 w0 = *(const float4*)&sW[b][0];
                float4 w1 = *(const float4*)&sW[b][4];
                float m = fmaxf(fmaxf(fmaxf(w0.x, w0.y), fmaxf(w0.z, w0.w)),
                                fmaxf(fmaxf(w1.x, w1.y), fmaxf(w1.z, w1.w)));
                Mv[b] = m;
                asm("rcp.approx.f32 %0, %1;" : "=f"(rinv[b]) : "f"(m));
            }
        }

        // dot: acc_j += alpha[i] * E[i][j], f32x2 over adjacent i
        unsigned long long accA[NB], accB[NB];
#pragma unroll
        for (int b = 0; b < NB; ++b) { accA[b] = 0ull; accB[b] = 0ull; }
#pragma unroll
        for (int c = 0; c < 8; ++c) {
#pragma unroll
            for (int b = 0; b < NB; ++b) {
                ulonglong2 v = *(const ulonglong2*)&sA[prv][b][AIDX(i0) + 4 * c];
                ffma2(accA[b], v.x, Ea[2 * c]);
                ffma2(accB[b], v.x, Eb[2 * c]);
                ffma2(accA[b], v.y, Ea[2 * c + 1]);
                ffma2(accB[b], v.y, Eb[2 * c + 1]);
            }
        }

        const bool dow = (((t + 1) & 3) == 0);  // publish maxima for next renorm
#pragma unroll
        for (int b = 0; b < NB; ++b) {
            float lo, hi;
            upk2(lo, hi, accA[b]); float dA = lo + hi;
            upk2(lo, hi, accB[b]); float dB = lo + hi;
            // reduce the 4 i-groups (lanes differ in bits 0-1)
            dA += __shfl_xor_sync(0xffffffffu, dA, 1);
            dA += __shfl_xor_sync(0xffffffffu, dA, 2);
            dB += __shfl_xor_sync(0xffffffffu, dB, 1);
            dB += __shfl_xor_sync(0xffffffffu, dB, 2);

            if (mkP0[b] != 0.0f) {
                float s0 = __expf(emP0[b].x);
                float s1 = __expf(emP0[b].y);
                if (renorm) { s0 *= rinv[b]; s1 *= rinv[b]; lg[b] += __logf(Mv[b]); }
                float nA = dA * s0, nB = dB * s1;
                if (ig == 0) *(float2*)&sA[cur][b][AIDX(j0)] = make_float2(nA, nB);
                if (dow) {
                    float wm = fmaxf(nA, nB);
#pragma unroll
                    for (int d = 16; d; d >>= 1)
                        wm = fmaxf(wm, __shfl_xor_sync(0xffffffffu, wm, d));
                    if (lane == 0) sW[b][wid] = wm;
                }
            } else {
                // masked step: alpha passes through unchanged (no division, no log)
                float2 old = *(const float2*)&sA[prv][b][AIDX(j0)];
                if (ig == 0) *(float2*)&sA[cur][b][AIDX(j0)] = old;
                if (dow) {
                    float wm = fmaxf(old.x, old.y);
#pragma unroll
                    for (int d = 16; d; d >>= 1)
                        wm = fmaxf(wm, __shfl_xor_sync(0xffffffffu, wm, d));
                    if (lane == 0) sW[b][wid] = wm;
                }
            }
        }

        // shift prefetch pipeline
#pragma unroll
        for (int b = 0; b < NB; ++b) {
            emP0[b] = emP1[b]; mkP0[b] = mkP1[b];
            emP1[b] = emN[b];  mkP1[b] = mkN[b];
        }
        __syncthreads();
    }

    // logZ = log(sum alpha_u) + accumulated log-scales
    if (wid < NB) {
        const int b = wid;
        float s = 0.0f;
#pragma unroll
        for (int k = 0; k < 4; ++k) s += sA[(SS - 1) & 1][b][AIDX(lane + 32 * k)];
#pragma unroll
        for (int d = 16; d; d >>= 1) s += __shfl_xor_sync(0xffffffffu, s, d);
        if (lane == 0) g_logZ[b0 + b] = __logf(s) + lg[b];
    }
}

// Gold-path score: emissions at tags + transitions between consecutive tags.
__global__ __launch_bounds__(128) void crf_score(
    const float* __restrict__ em, const float* __restrict__ tr,
    const int* __restrict__ tags, const float* __restrict__ mask)
{
    const int b = blockIdx.x;
    const int tid = threadIdx.x;
    const int* tg = tags + b * SS;
    const float* mk = mask + b * SS;
    float acc = 0.0f;
    for (int t = tid; t < SS; t += 128) {
        int c = tg[t];
        float m = mk[t];
        float v = em[((size_t)b * SS + t) * NT + c] * m;
        if (t > 0) v += tr[tg[t - 1] * NT + c] * m;
        acc += v;
    }
#pragma unroll
    for (int d = 16; d; d >>= 1) acc += __shfl_xor_sync(0xffffffffu, acc, d);
    __shared__ float red[4];
    if ((tid & 31) == 0) red[tid >> 5] = acc;
    __syncthreads();
    if (tid == 0) g_score[b] = red[0] + red[1] + red[2] + red[3];
}

__global__ __launch_bounds__(BB) void crf_final(float* __restrict__ out) {
    const int tid = threadIdx.x;
    float v = g_logZ[tid] - g_score[tid];
#pragma unroll
    for (int d = 16; d; d >>= 1) v += __shfl_xor_sync(0xffffffffu, v, d);
    __shared__ float red[8];
    if ((tid & 31) == 0) red[tid >> 5] = v;
    __syncthreads();
    if (tid == 0) {
        float s = 0.0f;
#pragma unroll
        for (int w = 0; w < 8; ++w) s += red[w];
        out[0] = s * (1.0f / BB);
    }
}

extern "C" void kernel_launch(void* const* d_in, const int* in_sizes, int n_in,
                              void* d_out, int out_size) {
    (void)in_sizes; (void)n_in; (void)out_size;
    const float* em   = (const float*)d_in[0];
    const float* tr   = (const float*)d_in[1];
    const int*   tags = (const int*)d_in[2];
    const float* mask = (const float*)d_in[3];
    crf_score<<<BB, 128>>>(em, tr, tags, mask);
    crf_forward<<<BB / NB, 256>>>(em, tr, mask);
    crf_final<<<1, BB>>>((float*)d_out);
}

// round 12
// speedup vs baseline: 2.4005x; 2.4005x over previous
#include <cuda_runtime.h>

#define BB 256
#define SS 1024
#define NT 128
#define CPRE 5.5f

__device__ float g_logZ[BB];
__device__ float g_score[BB];

static __device__ __forceinline__ unsigned long long pk2(float x, float y) {
    unsigned long long r;
    asm("mov.b64 %0, {%1, %2};" : "=l"(r) : "f"(x), "f"(y));
    return r;
}
static __device__ __forceinline__ void upk2(float& x, float& y, unsigned long long v) {
    asm("mov.b64 {%0, %1}, %2;" : "=f"(x), "=f"(y) : "l"(v));
}
static __device__ __forceinline__ void ffma2(unsigned long long& d, unsigned long long a, unsigned long long b) {
    asm("fma.rn.f32x2 %0, %1, %2, %0;" : "+l"(d) : "l"(a), "l"(b));
}

// Padded alpha index: i-group g starts at 36g floats -> the four groups' LDS.128
// hit disjoint bank quads (conflict-free), same-group lanes broadcast.
#define AIDX(i) ((i) + (((i) >> 5) << 2))

// Forward recurrence. 256 CTAs x 256 threads, 1 batch per CTA, 2 CTAs/SM
// (co-resident independent CTAs hide each other's barrier/chain stalls).
// Thread (ig=tid&3, jg=tid>>2) owns exp(T) rows [32ig,32ig+32) x cols {2jg,2jg+1}
// in registers, FFMA2-packed over adjacent i.
__global__ __launch_bounds__(256, 2) void crf_forward(
    const float* __restrict__ em, const float* __restrict__ tr,
    const float* __restrict__ mask)
{
    __shared__ __align__(16) float sA[2][144];
    __shared__ __align__(16) float sW[8];

    const int tid  = threadIdx.x;
    const int ig   = tid & 3;
    const int jg   = tid >> 2;
    const int i0   = ig << 5;
    const int j0   = jg << 1;
    const int lane = tid & 31;
    const int wid  = tid >> 5;
    const int b    = blockIdx.x;

    // exp(T) tile -> registers (T is L2-resident across all CTAs)
    unsigned long long Ea[16], Eb[16];
#pragma unroll
    for (int k = 0; k < 16; ++k) {
        float2 r0 = *(const float2*)(tr + (i0 + 2 * k) * NT + j0);
        float2 r1 = *(const float2*)(tr + (i0 + 2 * k + 1) * NT + j0);
        Ea[k] = pk2(__expf(r0.x), __expf(r1.x));
        Eb[k] = pk2(__expf(r0.y), __expf(r1.y));
    }

    const float* eb = em + (size_t)b * SS * NT;
    const float* mb = mask + b * SS;

    float lg = 0.0f;
    // t = 0 init: alpha = exp(emissions[:,0,:])
    {
        float2 e0 = *(const float2*)(eb + j0);
        if (ig == 0) *(float2*)&sA[0][AIDX(j0)] = make_float2(__expf(e0.x), __expf(e0.y));
    }

    // preload emissions/mask for steps 1..4 (consumed in first macro-iter)
    float2 emB[4]; float mkB[4];
#pragma unroll
    for (int u = 0; u < 4; ++u) {
        emB[u] = *(const float2*)(eb + (size_t)(1 + u) * NT + j0);
        mkB[u] = mb[1 + u];
    }
    __syncthreads();

    for (int tb = 1; tb < SS; tb += 4) {
        // prefetch steps tb+4 .. tb+7 (distance = 4 steps >> DRAM latency)
        float2 emN[4]; float mkN[4];
#pragma unroll
        for (int u = 0; u < 4; ++u) {
            int tp = tb + 4 + u; if (tp > SS - 1) tp = SS - 1;
            emN[u] = *(const float2*)(eb + (size_t)tp * NT + j0);
            mkN[u] = mb[tp];
        }

#pragma unroll
        for (int u = 0; u < 4; ++u) {
            const int t = tb + u;
            if (t < SS) {   // uniform guard (only trims t=1024 in last macro-iter)
                const int cur = t & 1, prv = cur ^ 1;
                const bool renorm = ((t & 31) == 0);        // t = 32, 64, ...
                const bool dow    = (((t + 1) & 31) == 0);  // publish max at t = 31, 63, ...

                float rinv = 1.0f, Mv = 1.0f;
                if (renorm) {
                    float4 w0 = *(const float4*)&sW[0];
                    float4 w1 = *(const float4*)&sW[4];
                    Mv = fmaxf(fmaxf(fmaxf(w0.x, w0.y), fmaxf(w0.z, w0.w)),
                               fmaxf(fmaxf(w1.x, w1.y), fmaxf(w1.z, w1.w)));
                    asm("rcp.approx.f32 %0, %1;" : "=f"(rinv) : "f"(Mv));
                }

                // acc_j += alpha[i] * E[i][j], FFMA2 over adjacent i
                unsigned long long accA = 0ull, accB = 0ull;
#pragma unroll
                for (int c = 0; c < 8; ++c) {
                    ulonglong2 v = *(const ulonglong2*)&sA[prv][AIDX(i0) + 4 * c];
                    ffma2(accA, v.x, Ea[2 * c]);
                    ffma2(accB, v.x, Eb[2 * c]);
                    ffma2(accA, v.y, Ea[2 * c + 1]);
                    ffma2(accB, v.y, Eb[2 * c + 1]);
                }
                float lo, hi;
                upk2(lo, hi, accA); float dA = lo + hi;
                upk2(lo, hi, accB); float dB = lo + hi;
                dA += __shfl_xor_sync(0xffffffffu, dA, 1);
                dA += __shfl_xor_sync(0xffffffffu, dA, 2);
                dB += __shfl_xor_sync(0xffffffffu, dB, 1);
                dB += __shfl_xor_sync(0xffffffffu, dB, 2);

                if (mkB[u] != 0.0f) {
                    float s0 = __expf(emB[u].x - CPRE);  // constant pre-scale, free FADD
                    float s1 = __expf(emB[u].y - CPRE);
                    lg += CPRE;
                    if (renorm) { s0 *= rinv; s1 *= rinv; lg += __logf(Mv); }
                    float nA = dA * s0, nB = dB * s1;
                    if (ig == 0) *(float2*)&sA[cur][AIDX(j0)] = make_float2(nA, nB);
                    if (dow) {
                        float wm = fmaxf(nA, nB);
#pragma unroll
                        for (int d = 16; d; d >>= 1)
                            wm = fmaxf(wm, __shfl_xor_sync(0xffffffffu, wm, d));
                        if (lane == 0) sW[wid] = wm;
                    }
                } else {
                    float2 old = *(const float2*)&sA[prv][AIDX(j0)];
                    if (ig == 0) *(float2*)&sA[cur][AIDX(j0)] = old;
                    if (dow) {
                        float wm = fmaxf(old.x, old.y);
#pragma unroll
                        for (int d = 16; d; d >>= 1)
                            wm = fmaxf(wm, __shfl_xor_sync(0xffffffffu, wm, d));
                        if (lane == 0) sW[wid] = wm;
                    }
                }
            }
            __syncthreads();
        }

#pragma unroll
        for (int u = 0; u < 4; ++u) { emB[u] = emN[u]; mkB[u] = mkN[u]; }
    }

    // logZ = log(sum alpha) + accumulated log-scales (t=1023 wrote sA[1])
    if (wid == 0) {
        float s = 0.0f;
#pragma unroll
        for (int k = 0; k < 4; ++k) s += sA[1][AIDX(lane + 32 * k)];
#pragma unroll
        for (int d = 16; d; d >>= 1) s += __shfl_xor_sync(0xffffffffu, s, d);
        if (lane == 0) g_logZ[b] = __logf(s) + lg;
    }
}

// Gold-path score: 256 threads x 4 contiguous timesteps -> int4/float4 loads,
// ~9 independent loads in flight per thread.
__global__ __launch_bounds__(256) void crf_score(
    const float* __restrict__ em, const float* __restrict__ tr,
    const int* __restrict__ tags, const float* __restrict__ mask)
{
    const int b = blockIdx.x;
    const int tid = threadIdx.x;
    const int t0 = tid * 4;
    const int* tg = tags + b * SS;
    const float* mk = mask + b * SS;
    const float* ebase = em + (size_t)b * SS * NT;

    int4   tg4 = *(const int4*)(tg + t0);
    float4 mk4 = *(const float4*)(mk + t0);

    float e0 = ebase[(size_t)(t0 + 0) * NT + tg4.x];
    float e1 = ebase[(size_t)(t0 + 1) * NT + tg4.y];
    float e2 = ebase[(size_t)(t0 + 2) * NT + tg4.z];
    float e3 = ebase[(size_t)(t0 + 3) * NT + tg4.w];

    float r0 = 0.0f;
    if (t0 > 0) { int tp = tg[t0 - 1]; r0 = tr[tp * NT + tg4.x]; }
    float r1 = tr[tg4.x * NT + tg4.y];
    float r2 = tr[tg4.y * NT + tg4.z];
    float r3 = tr[tg4.z * NT + tg4.w];

    float acc = (e0 + r0) * mk4.x + (e1 + r1) * mk4.y
              + (e2 + r2) * mk4.z + (e3 + r3) * mk4.w;

#pragma unroll
    for (int d = 16; d; d >>= 1) acc += __shfl_xor_sync(0xffffffffu, acc, d);
    __shared__ float red[8];
    if ((tid & 31) == 0) red[tid >> 5] = acc;
    __syncthreads();
    if (tid == 0) {
        float s = 0.0f;
#pragma unroll
        for (int w = 0; w < 8; ++w) s += red[w];
        g_score[b] = s;
    }
}

__global__ __launch_bounds__(BB) void crf_final(float* __restrict__ out) {
    const int tid = threadIdx.x;
    float v = g_logZ[tid] - g_score[tid];
#pragma unroll
    for (int d = 16; d; d >>= 1) v += __shfl_xor_sync(0xffffffffu, v, d);
    __shared__ float red[8];
    if ((tid & 31) == 0) red[tid >> 5] = v;
    __syncthreads();
    if (tid == 0) {
        float s = 0.0f;
#pragma unroll
        for (int w = 0; w < 8; ++w) s += red[w];
        out[0] = s * (1.0f / BB);
    }
}

extern "C" void kernel_launch(void* const* d_in, const int* in_sizes, int n_in,
                              void* d_out, int out_size) {
    (void)in_sizes; (void)n_in; (void)out_size;
    const float* em   = (const float*)d_in[0];
    const float* tr   = (const float*)d_in[1];
    const int*   tags = (const int*)d_in[2];
    const float* mask = (const float*)d_in[3];
    crf_score<<<BB, 256>>>(em, tr, tags, mask);
    crf_forward<<<BB, 256>>>(em, tr, mask);
    crf_final<<<1, BB>>>((float*)d_out);
}